// round 16
// baseline (speedup 1.0000x reference)
#include <cuda_runtime.h>
#include <cuda_bf16.h>
#include <math.h>
#include <stdint.h>

// ---------------------------------------------------------------------------
// MultiModalFusionGAT — mma.sync bf16x3 GEMM + CSR-gather edge phase.
//  * weight fragments interleaved {hi0,hi1,lo0,lo1} per lane -> single
//    LDS.128 per (kc,nt) instead of two LDS.64 (issue-bound inner loop)
//  * scan vectorized int4 (13 serial block-iterations instead of 49)
//  * persistent projection + output GEMMs (R12/R14 winners), hist fused
// ---------------------------------------------------------------------------

#define HID 128

// scratch layout (floats)
#define OFF_Q_USER   0ll
#define OFF_Q_ITEM   2560000ll
#define OFF_KV_USER  8960000ll    // 20000 * 256 (kr | vr interleaved)
#define OFF_KV_ITEM  14080000ll   // 50000 * 256
#define OFF_KV_TASTE 26880000ll   // 50000 * 256
#define OFF_KV_IMAGE 39680000ll   // 50000 * 256
#define OFF_CSRBASE  52480000ll   // int region
#define OFF_GEL_ITEM 62000000ll
#define OFF_GEL_USER 68400000ll
#define OFF_WFRAG    70960000ll   // 12 mats x 16384 u32 (hi/lo interleaved)
#define OFF_BIAS     71156608ll   // 12 x 128 floats
#define SCRATCH_TOTAL 71158144ll

// int offsets inside the CSR region (units: int32)
#define ICSR_I   0          // 600000 entries (item edges, packed src|seg<<16)
#define ICSR_U   600000     // 500000 entries (user edges, src)
#define ISTART_I 1100000    // 50001
#define ISTART_U 1150004    // 20001
#define ICNT_I   1170008    // 50000
#define ICNT_U   1220008    // 20000  (cnt arrays contiguous: 70000 total)

#define NCTA_GEMM 296       // persistent GEMM CTAs (2 per SM, one wave)
#define GEMM_SMEM 65536

__device__ float g_scratch[SCRATCH_TOTAL];

struct EdgeIO {
    const int* src[4];
    const int* dst[4];
    int off[5];
};

struct GemmBatch {
    const float* X[10];
    const uint32_t* W[10];
    const float* B[10];
    float* Y[10];
    int N[10];
    int YS[10];        // output row stride (floats)
    int tileStart[11]; // prefix sums of per-matrix tile counts
    int chunk;         // tiles per persistent CTA
    EdgeIO E;          // for the fused hist slice (blockIdx.y == 1)
    int* cntI;
    int* cntU;
};

struct OutBatch {
    const float* X[2];
    const uint32_t* W[2];
    const float* B[2];
    float* Y[2];
    const float* Res[2];
    const float* Skip;
    int N[2];
    int tileStart[3];
    int chunk;
};

struct GatherIO {
    const float* Qi; const float* Qu;
    const float* KV[4];           // interleaved kr|vr, 256 floats/node
    const int* csrI; const int* csrU;
    const int* startI; const int* startU;
    float* gelI; float* gelU;
    const float* prel;
    int nI, nU;
};

// ---------------------------------------------------------------------------
__device__ __forceinline__ float foldW(int m, int k, int n,
        const float* __restrict__ Wk, const float* __restrict__ Wv,
        const float* __restrict__ Wq, const float* __restrict__ Wo,
        const float* __restrict__ a_rel, const float* __restrict__ m_rel) {
    if (m < 8) {
        int r = m & 3;
        int h = n >> 4, e = n & 15;
        int tsrc = (r == 0) ? 2 : (r == 1) ? 3 : (r == 2) ? 0 : 1;
        const float* Wsrc = (m < 4) ? Wk : Wv;
        const float* rel  = (m < 4) ? a_rel : m_rel;
        const float* wrow = Wsrc + tsrc * 16384 + k * 128 + h * 16;
        const float* arow = rel + r * 2048 + h * 256;
        float s = 0.f;
        #pragma unroll
        for (int d = 0; d < 16; d++) s += wrow[d] * arow[d * 16 + e];
        return s;
    } else if (m < 10) {
        return Wq[(m - 8) * 16384 + k * 128 + n];
    }
    return Wo[(m - 10) * 16384 + k * 128 + n];
}

__device__ __forceinline__ uint32_t packbf2(float a, float b) {
    __nv_bfloat16 ha = __float2bfloat16(a), hb = __float2bfloat16(b);
    return (uint32_t)__bfloat16_as_ushort(ha)
         | ((uint32_t)__bfloat16_as_ushort(hb) << 16);
}

// prep: weights -> INTERLEAVED fragment layout {hi_r0, hi_r1, lo_r0, lo_r1}
// per (kc,nt,lane); bias fold; CSR counter zeroing (fused)
#define PREP_W   98304
#define PREP_B   (PREP_W + 1536)
#define PREP_Z   (PREP_B + 70000)
__global__ void prep_kernel(const float* __restrict__ Wk, const float* __restrict__ bk,
                            const float* __restrict__ Wq, const float* __restrict__ bq,
                            const float* __restrict__ Wv, const float* __restrict__ bv,
                            const float* __restrict__ a_rel, const float* __restrict__ m_rel,
                            const float* __restrict__ Wo, const float* __restrict__ bo,
                            uint32_t* __restrict__ Wfrag, float* __restrict__ Bias,
                            int* __restrict__ cnt) {
    int idx = blockIdx.x * blockDim.x + threadIdx.x;
    if (idx < PREP_W) {
        int m = idx >> 13;
        int rest = idx & 8191;
        int kc = rest >> 10;
        int rest2 = rest & 1023;
        int nt = rest2 >> 6;
        int e  = rest2 & 63;
        int lane = e >> 1, r = e & 1;
        int n  = nt * 8 + (lane >> 2);
        int k0 = kc * 16 + (lane & 3) * 2 + r * 8;
        float v0 = foldW(m, k0,     n, Wk, Wv, Wq, Wo, a_rel, m_rel);
        float v1 = foldW(m, k0 + 1, n, Wk, Wv, Wq, Wo, a_rel, m_rel);
        __nv_bfloat16 h0 = __float2bfloat16(v0), h1 = __float2bfloat16(v1);
        float l0 = v0 - __bfloat162float(h0), l1 = v1 - __bfloat162float(h1);
        uint32_t hi = (uint32_t)__bfloat16_as_ushort(h0)
                    | ((uint32_t)__bfloat16_as_ushort(h1) << 16);
        uint32_t lo = packbf2(l0, l1);
        size_t pos = (size_t)m * 16384 + (size_t)((kc * 16 + nt) * 32 + lane) * 4;
        Wfrag[pos + r] = hi;
        Wfrag[pos + 2 + r] = lo;
    } else if (idx < PREP_B) {
        int j = idx - PREP_W;
        int m = j >> 7, n = j & 127;
        float bval;
        if (m < 8) {
            int r = m & 3;
            int h = n >> 4, e2 = n & 15;
            int tsrc = (r == 0) ? 2 : (r == 1) ? 3 : (r == 2) ? 0 : 1;
            const float* bsrc = (m < 4) ? bk : bv;
            const float* rel  = (m < 4) ? a_rel : m_rel;
            const float* brow = bsrc + tsrc * 128 + h * 16;
            const float* arow = rel + r * 2048 + h * 256;
            float sb = 0.f;
            #pragma unroll
            for (int d = 0; d < 16; d++) sb += brow[d] * arow[d * 16 + e2];
            bval = sb;
        } else if (m < 10) {
            bval = bq[(m - 8) * 128 + n];
        } else {
            bval = bo[(m - 10) * 128 + n];
        }
        Bias[m * 128 + n] = bval;
    } else if (idx < PREP_Z) {
        cnt[idx - PREP_B] = 0;   // cntI | cntU contiguous (70000 ints)
    }
}

// ---------------------------------------------------------------------------
__device__ __forceinline__ void mma16816(float c[4], const uint32_t a[4],
                                         uint32_t b0, uint32_t b1) {
    asm volatile(
        "mma.sync.aligned.m16n8k16.row.col.f32.bf16.bf16.f32 "
        "{%0,%1,%2,%3}, {%4,%5,%6,%7}, {%8,%9}, {%0,%1,%2,%3};"
        : "+f"(c[0]), "+f"(c[1]), "+f"(c[2]), "+f"(c[3])
        : "r"(a[0]), "r"(a[1]), "r"(a[2]), "r"(a[3]), "r"(b0), "r"(b1));
}

__device__ __forceinline__ void split4(const float2& a, const float2& b,
                                       uint32_t& h01, uint32_t& l01,
                                       uint32_t& h23, uint32_t& l23) {
    __nv_bfloat16 ha = __float2bfloat16(a.x), hb = __float2bfloat16(a.y);
    __nv_bfloat16 hc = __float2bfloat16(b.x), hd = __float2bfloat16(b.y);
    h01 = (uint32_t)__bfloat16_as_ushort(ha) | ((uint32_t)__bfloat16_as_ushort(hb) << 16);
    h23 = (uint32_t)__bfloat16_as_ushort(hc) | ((uint32_t)__bfloat16_as_ushort(hd) << 16);
    l01 = packbf2(a.x - __bfloat162float(ha), a.y - __bfloat162float(hb));
    l23 = packbf2(b.x - __bfloat162float(hc), b.y - __bfloat162float(hd));
}

// Core 128x128 tile GEMM (bf16x3), pipelined kc loop; LDS.128 B-fragments.
__device__ __forceinline__ void gemm_tile(
        const float* __restrict__ X, const uint32_t* __restrict__ sW,
        const float* __restrict__ Bias, float* __restrict__ Y, int N, int tile0,
        int ystride, int mode, const float* __restrict__ Res, float g, float omg) {
    int tid = threadIdx.x;
    int warp = tid >> 5, lane = tid & 31;
    int rlo = tile0 + warp * 16 + (lane >> 2);
    int rhi = rlo + 8;
    bool oklo = rlo < N, okhi = rhi < N;
    const float* xlo = X + (size_t)rlo * 128;
    const float* xhi = X + (size_t)rhi * 128;
    int kb = (lane & 3) * 2;

    float C[16][4];
    #pragma unroll
    for (int nt = 0; nt < 16; nt++)
        #pragma unroll
        for (int j = 0; j < 4; j++) C[nt][j] = 0.f;

    float2 z2 = make_float2(0.f, 0.f);
    float2 p00 = oklo ? *(const float2*)(xlo + kb)     : z2;
    float2 p01 = oklo ? *(const float2*)(xlo + kb + 8) : z2;
    float2 p10 = okhi ? *(const float2*)(xhi + kb)     : z2;
    float2 p11 = okhi ? *(const float2*)(xhi + kb + 8) : z2;

    #pragma unroll 1
    for (int kc = 0; kc < 8; kc++) {
        float2 c00 = p00, c01 = p01, c10 = p10, c11 = p11;
        if (kc < 7) {
            int o = (kc + 1) * 16 + kb;
            p00 = oklo ? *(const float2*)(xlo + o)     : z2;
            p01 = oklo ? *(const float2*)(xlo + o + 8) : z2;
            p10 = okhi ? *(const float2*)(xhi + o)     : z2;
            p11 = okhi ? *(const float2*)(xhi + o + 8) : z2;
        }
        uint32_t ahi[4], alo[4];
        split4(c00, c10, ahi[0], alo[0], ahi[1], alo[1]);
        split4(c01, c11, ahi[2], alo[2], ahi[3], alo[3]);
        #pragma unroll
        for (int nt = 0; nt < 16; nt++) {
            uint32_t off = (uint32_t)(((kc * 16 + nt) * 32 + lane) * 4);
            uint4 b = *(const uint4*)&sW[off];
            mma16816(C[nt], ahi, b.x, b.y);
            mma16816(C[nt], alo, b.x, b.y);
            mma16816(C[nt], ahi, b.z, b.w);
        }
    }

    #pragma unroll
    for (int nt = 0; nt < 16; nt++) {
        int col = nt * 8 + kb;
        float2 b = *(const float2*)(Bias + col);
        if (oklo) {
            float2 o = make_float2(C[nt][0] + b.x, C[nt][1] + b.y);
            if (mode == 1) {
                float2 rv = *(const float2*)(Res + (size_t)rlo * 128 + col);
                o.x = g * o.x + omg * rv.x;
                o.y = g * o.y + omg * rv.y;
            }
            *(float2*)(Y + (size_t)rlo * ystride + col) = o;
        }
        if (okhi) {
            float2 o = make_float2(C[nt][2] + b.x, C[nt][3] + b.y);
            if (mode == 1) {
                float2 rv = *(const float2*)(Res + (size_t)rhi * 128 + col);
                o.x = g * o.x + omg * rv.x;
                o.y = g * o.y + omg * rv.y;
            }
            *(float2*)(Y + (size_t)rhi * ystride + col) = o;
        }
    }
}

// persistent batched projections (grid.y==0) + fused hist (grid.y==1)
__global__ void __launch_bounds__(256) mma_gemm_batch(GemmBatch P) {
    if (blockIdx.y == 1) {
        int total = P.E.off[4];
        int stride = gridDim.x * 256;
        for (int g = blockIdx.x * 256 + threadIdx.x; g < total; g += stride) {
            int seg = (g >= P.E.off[1]) + (g >= P.E.off[2]) + (g >= P.E.off[3]);
            int e = g - P.E.off[seg];
            int d = P.E.dst[seg][e];
            atomicAdd((seg < 3) ? (P.cntI + d) : (P.cntU + d), 1);
        }
        return;
    }
    extern __shared__ uint32_t sW[];
    int total = P.tileStart[10];
    int t0 = blockIdx.x * P.chunk;
    int t1 = t0 + P.chunk;
    if (t1 > total) t1 = total;
    int cur = -1;
    for (int t = t0; t < t1; t++) {
        if (cur < 0 || t >= P.tileStart[cur + 1]) {
            int m = (cur < 0) ? 0 : cur + 1;
            while (t >= P.tileStart[m + 1]) m++;
            __syncthreads();   // all warps done reading old weights
            const uint4* src = (const uint4*)P.W[m];
            uint4* dst = (uint4*)sW;
            int tid = threadIdx.x;
            #pragma unroll
            for (int i = 0; i < 16; i++) dst[tid + i * 256] = src[tid + i * 256];
            __syncthreads();
            cur = m;
        }
        gemm_tile(P.X[cur], sW, P.B[cur], P.Y[cur], P.N[cur],
                  (t - P.tileStart[cur]) * 128, P.YS[cur], 0, nullptr, 1.f, 0.f);
    }
}

// persistent fused output GEMMs with sigmoid-gated residual
__global__ void __launch_bounds__(256) mma_gemm_out(OutBatch P) {
    extern __shared__ uint32_t sW[];
    int total = P.tileStart[2];
    int t0 = blockIdx.x * P.chunk;
    int t1 = t0 + P.chunk;
    if (t1 > total) t1 = total;
    int cur = -1;
    float g = 1.f, omg = 0.f;
    for (int t = t0; t < t1; t++) {
        if (cur < 0 || t >= P.tileStart[cur + 1]) {
            int m = (cur < 0) ? 0 : cur + 1;
            while (t >= P.tileStart[m + 1]) m++;
            __syncthreads();
            const uint4* src = (const uint4*)P.W[m];
            uint4* dst = (uint4*)sW;
            int tid = threadIdx.x;
            #pragma unroll
            for (int i = 0; i < 16; i++) dst[tid + i * 256] = src[tid + i * 256];
            __syncthreads();
            cur = m;
            g = 1.f / (1.f + expf(-P.Skip[m]));
            omg = 1.f - g;
        }
        gemm_tile(P.X[cur], sW, P.B[cur], P.Y[cur], P.N[cur],
                  (t - P.tileStart[cur]) * 128, 128, 1, P.Res[cur], g, omg);
    }
}

// ---------------------------------------------------------------------------
// vectorized block scan (int4, 4096 elements per iteration); resets cnt to 0
__global__ void scan_kernel(int* __restrict__ cntI, int* __restrict__ startI, int nI,
                            int* __restrict__ cntU, int* __restrict__ startU, int nU) {
    int* cnt   = blockIdx.x ? cntU : cntI;
    int* start = blockIdx.x ? startU : startI;
    int n      = blockIdx.x ? nU : nI;     // multiple of 4
    __shared__ int wsum[32];
    __shared__ int s_carry;
    int tid = threadIdx.x, lane = tid & 31, wid = tid >> 5;
    if (tid == 0) s_carry = 0;
    __syncthreads();
    for (int base = 0; base < n; base += 4096) {
        int i4 = base + tid * 4;
        int4 v = make_int4(0, 0, 0, 0);
        if (i4 < n) {
            v = *(const int4*)(cnt + i4);
            *(int4*)(cnt + i4) = make_int4(0, 0, 0, 0);
        }
        int s = v.x + v.y + v.z + v.w;
        int incl = s;
        #pragma unroll
        for (int o = 1; o < 32; o <<= 1) {
            int t = __shfl_up_sync(0xFFFFFFFFu, incl, o);
            if (lane >= o) incl += t;
        }
        if (lane == 31) wsum[wid] = incl;
        __syncthreads();
        if (wid == 0) {
            int w = wsum[lane];
            int wi = w;
            #pragma unroll
            for (int o = 1; o < 32; o <<= 1) {
                int t = __shfl_up_sync(0xFFFFFFFFu, wi, o);
                if (lane >= o) wi += t;
            }
            wsum[lane] = wi - w;
        }
        __syncthreads();
        int excl = incl - s + wsum[wid] + s_carry;
        if (i4 < n) {
            int4 o;
            o.x = excl;
            o.y = excl + v.x;
            o.z = o.y + v.y;
            o.w = o.z + v.z;
            *(int4*)(start + i4) = o;
        }
        __syncthreads();
        if (tid == 1023) s_carry = excl + s;
        __syncthreads();
    }
    if (tid == 0) start[n] = s_carry;
}

__global__ void scatter_kernel(EdgeIO E,
                               const int* __restrict__ startI, const int* __restrict__ startU,
                               int* __restrict__ cntI, int* __restrict__ cntU,
                               int* __restrict__ csrI, int* __restrict__ csrU) {
    int g = blockIdx.x * 256 + threadIdx.x;
    if (g >= E.off[4]) return;
    int seg = (g >= E.off[1]) + (g >= E.off[2]) + (g >= E.off[3]);
    int e = g - E.off[seg];
    int d = E.dst[seg][e];
    int s = E.src[seg][e];
    if (seg < 3) {
        int pos = startI[d] + atomicAdd(cntI + d, 1);
        csrI[pos] = s | (seg << 16);
    } else {
        int pos = startU[d] + atomicAdd(cntU + d, 1);
        csrU[pos] = s;
    }
}

// warp-per-dst gather, unrolled x2: softmax aggregate + inline GELU
__global__ void __launch_bounds__(256) gather_kernel(GatherIO P) {
    int w = blockIdx.x * 8 + (threadIdx.x >> 5);
    int lane = threadIdx.x & 31;
    int h = lane >> 2;
    bool item = w < P.nI;
    int d = item ? w : w - P.nI;
    if (!item && d >= P.nU) return;

    const float* q = (item ? P.Qi : P.Qu) + (size_t)d * 128;
    float4 qv = *(const float4*)(q + lane * 4);
    const int* csr = item ? P.csrI : P.csrU;
    int js = item ? P.startI[d] : P.startU[d];
    int je = item ? P.startI[d + 1] : P.startU[d + 1];
    float p0, p1, p2;
    if (item) { p0 = P.prel[h]; p1 = P.prel[8 + h]; p2 = P.prel[16 + h]; }
    else      { p0 = p1 = p2 = P.prel[24 + h]; }

    float4 acc = make_float4(0.f, 0.f, 0.f, 0.f);
    float den = 0.f;
    int j = js;
    for (; j + 1 < je; j += 2) {
        int e0 = csr[j], e1 = csr[j + 1];
        int s0 = e0 & 0xFFFF, s1 = e1 & 0xFFFF;
        int g0 = item ? (e0 >> 16) : 3, g1 = item ? (e1 >> 16) : 3;
        const float* kv0b = P.KV[g0] + (size_t)s0 * 256;
        const float* kv1b = P.KV[g1] + (size_t)s1 * 256;
        float4 k0 = *(const float4*)(kv0b + lane * 4);
        float4 v0 = *(const float4*)(kv0b + 128 + lane * 4);
        float4 k1 = *(const float4*)(kv1b + lane * 4);
        float4 v1 = *(const float4*)(kv1b + 128 + lane * 4);
        float pa = qv.x * k0.x + qv.y * k0.y + qv.z * k0.z + qv.w * k0.w;
        float pb = qv.x * k1.x + qv.y * k1.y + qv.z * k1.z + qv.w * k1.w;
        pa += __shfl_xor_sync(0xFFFFFFFFu, pa, 1);
        pb += __shfl_xor_sync(0xFFFFFFFFu, pb, 1);
        pa += __shfl_xor_sync(0xFFFFFFFFu, pa, 2);
        pb += __shfl_xor_sync(0xFFFFFFFFu, pb, 2);
        float pr0 = item ? ((g0 == 0) ? p0 : ((g0 == 1) ? p1 : p2)) : p0;
        float pr1 = item ? ((g1 == 0) ? p0 : ((g1 == 1) ? p1 : p2)) : p0;
        float ex0 = __expf(pa * pr0 * 0.25f);
        float ex1 = __expf(pb * pr1 * 0.25f);
        den += ex0 + ex1;
        acc.x += ex0 * v0.x + ex1 * v1.x;
        acc.y += ex0 * v0.y + ex1 * v1.y;
        acc.z += ex0 * v0.z + ex1 * v1.z;
        acc.w += ex0 * v0.w + ex1 * v1.w;
    }
    if (j < je) {
        int e0 = csr[j];
        int s0 = e0 & 0xFFFF;
        int g0 = item ? (e0 >> 16) : 3;
        const float* kv0b = P.KV[g0] + (size_t)s0 * 256;
        float4 k0 = *(const float4*)(kv0b + lane * 4);
        float4 v0 = *(const float4*)(kv0b + 128 + lane * 4);
        float pa = qv.x * k0.x + qv.y * k0.y + qv.z * k0.z + qv.w * k0.w;
        pa += __shfl_xor_sync(0xFFFFFFFFu, pa, 1);
        pa += __shfl_xor_sync(0xFFFFFFFFu, pa, 2);
        float pr0 = item ? ((g0 == 0) ? p0 : ((g0 == 1) ? p1 : p2)) : p0;
        float ex0 = __expf(pa * pr0 * 0.25f);
        den += ex0;
        acc.x += ex0 * v0.x; acc.y += ex0 * v0.y;
        acc.z += ex0 * v0.z; acc.w += ex0 * v0.w;
    }
    float inv = 1.f / (den + 1e-16f);
    const float RS2 = 0.70710678118654752f;
    float4 o;
    float v;
    v = acc.x * inv; o.x = 0.5f * v * (1.f + erff(v * RS2));
    v = acc.y * inv; o.y = 0.5f * v * (1.f + erff(v * RS2));
    v = acc.z * inv; o.z = 0.5f * v * (1.f + erff(v * RS2));
    v = acc.w * inv; o.w = 0.5f * v * (1.f + erff(v * RS2));
    float* out = (item ? P.gelI : P.gelU) + (size_t)d * 128 + lane * 4;
    *(float4*)out = o;
}

// ---------------------------------------------------------------------------
extern "C" void kernel_launch(void* const* d_in, const int* in_sizes, int n_in,
                              void* d_out, int out_size) {
    const float* x_user = (const float*)d_in[0];
    const float* x_item = (const float*)d_in[1];
    const float* x_taste = (const float*)d_in[2];
    const float* x_image = (const float*)d_in[3];
    const float* Wk = (const float*)d_in[4];
    const float* bk = (const float*)d_in[5];
    const float* Wq = (const float*)d_in[6];
    const float* bq = (const float*)d_in[7];
    const float* Wv = (const float*)d_in[8];
    const float* bv = (const float*)d_in[9];
    const float* a_rel = (const float*)d_in[10];
    const float* m_rel = (const float*)d_in[11];
    const float* p_rel = (const float*)d_in[12];
    const float* Wo = (const float*)d_in[13];
    const float* bo = (const float*)d_in[14];
    const float* skip = (const float*)d_in[15];
    const int* ti_src = (const int*)d_in[16];
    const int* ti_dst = (const int*)d_in[17];
    const int* im_src = (const int*)d_in[18];
    const int* im_dst = (const int*)d_in[19];
    const int* ub_src = (const int*)d_in[20];
    const int* ub_dst = (const int*)d_in[21];
    const int* bu_src = (const int*)d_in[22];
    const int* bu_dst = (const int*)d_in[23];

    int nUser = in_sizes[0] / HID;
    int nItem = in_sizes[1] / HID;
    int nTaste = in_sizes[2] / HID;
    int nImage = in_sizes[3] / HID;
    int eTI = in_sizes[16], eIM = in_sizes[18], eUB = in_sizes[20], eBU = in_sizes[22];

    float* S = nullptr;
    cudaGetSymbolAddress((void**)&S, g_scratch);
    uint32_t* Wfrag = (uint32_t*)(S + OFF_WFRAG);
    float* Bias = S + OFF_BIAS;
    int* I = (int*)(S + OFF_CSRBASE);

    cudaFuncSetAttribute(mma_gemm_batch,
                         cudaFuncAttributeMaxDynamicSharedMemorySize, GEMM_SMEM);
    cudaFuncSetAttribute(mma_gemm_out,
                         cudaFuncAttributeMaxDynamicSharedMemorySize, GEMM_SMEM);

    // edge tables
    EdgeIO E;
    E.src[0] = ti_src; E.dst[0] = ti_dst;
    E.src[1] = im_src; E.dst[1] = im_dst;
    E.src[2] = ub_src; E.dst[2] = ub_dst;
    E.src[3] = bu_src; E.dst[3] = bu_dst;
    E.off[0] = 0;
    E.off[1] = eTI;
    E.off[2] = eTI + eIM;
    E.off[3] = eTI + eIM + eUB;
    E.off[4] = eTI + eIM + eUB + eBU;
    int eTotal = E.off[4];

    // 1) prep weights + bias + zero CSR counters (one launch)
    prep_kernel<<<(PREP_Z + 255) / 256, 256>>>(
        Wk, bk, Wq, bq, Wv, bv, a_rel, m_rel, Wo, bo, Wfrag, Bias, I + ICNT_I);

    // 2) persistent projection GEMMs + hist, one launch
    GemmBatch GB;
    const float* xs[10] = {x_user, x_item, x_user, x_user, x_item,
                           x_item, x_taste, x_taste, x_image, x_image};
    int mats[10]        = {8, 9, 2, 6, 3, 7, 0, 4, 1, 5};
    long long offs[10]  = {OFF_Q_USER, OFF_Q_ITEM,
                           OFF_KV_USER, OFF_KV_USER + 128,
                           OFF_KV_ITEM, OFF_KV_ITEM + 128,
                           OFF_KV_TASTE, OFF_KV_TASTE + 128,
                           OFF_KV_IMAGE, OFF_KV_IMAGE + 128};
    int strides[10] = {128, 128, 256, 256, 256, 256, 256, 256, 256, 256};
    int ns[10] = {nUser, nItem, nUser, nUser, nItem, nItem, nTaste, nTaste, nImage, nImage};
    int tsum = 0;
    for (int i = 0; i < 10; i++) {
        GB.X[i] = xs[i];
        GB.W[i] = Wfrag + (size_t)mats[i] * 16384;
        GB.B[i] = Bias + mats[i] * 128;
        GB.Y[i] = S + offs[i];
        GB.N[i] = ns[i];
        GB.YS[i] = strides[i];
        GB.tileStart[i] = tsum;
        tsum += (ns[i] + 127) / 128;
    }
    GB.tileStart[10] = tsum;
    GB.chunk = (tsum + NCTA_GEMM - 1) / NCTA_GEMM;
    GB.E = E;
    GB.cntI = I + ICNT_I;
    GB.cntU = I + ICNT_U;
    mma_gemm_batch<<<dim3(NCTA_GEMM, 2), 256, GEMM_SMEM>>>(GB);

    // 3) CSR: scan + scatter
    scan_kernel<<<2, 1024>>>(I + ICNT_I, I + ISTART_I, nItem,
                             I + ICNT_U, I + ISTART_U, nUser);
    scatter_kernel<<<(eTotal + 255) / 256, 256>>>(E, I + ISTART_I, I + ISTART_U,
                                                  I + ICNT_I, I + ICNT_U,
                                                  I + ICSR_I, I + ICSR_U);

    // 4) gather: softmax aggregate + GELU
    GatherIO G;
    G.Qi = S + OFF_Q_ITEM;
    G.Qu = S + OFF_Q_USER;
    G.KV[0] = S + OFF_KV_TASTE;
    G.KV[1] = S + OFF_KV_IMAGE;
    G.KV[2] = S + OFF_KV_USER;
    G.KV[3] = S + OFF_KV_ITEM;
    G.csrI = I + ICSR_I;   G.csrU = I + ICSR_U;
    G.startI = I + ISTART_I; G.startU = I + ISTART_U;
    G.gelI = S + OFF_GEL_ITEM; G.gelU = S + OFF_GEL_USER;
    G.prel = p_rel;
    G.nI = nItem; G.nU = nUser;
    int warps = nItem + nUser;
    gather_kernel<<<(warps + 7) / 8, 256>>>(G);

    // 5) persistent fused output projections with sigmoid-gated residual
    float* out_i = (float*)d_out;
    float* out_u = (float*)d_out + (size_t)nItem * HID;
    OutBatch OB;
    OB.X[0] = S + OFF_GEL_ITEM; OB.X[1] = S + OFF_GEL_USER;
    OB.W[0] = Wfrag + 10ull * 16384; OB.W[1] = Wfrag + 11ull * 16384;
    OB.B[0] = Bias + 10 * 128; OB.B[1] = Bias + 11 * 128;
    OB.Y[0] = out_i; OB.Y[1] = out_u;
    OB.Res[0] = x_item; OB.Res[1] = x_user;
    OB.Skip = skip;
    OB.N[0] = nItem; OB.N[1] = nUser;
    int tI = (nItem + 127) / 128, tU = (nUser + 127) / 128;
    OB.tileStart[0] = 0;
    OB.tileStart[1] = tI;
    OB.tileStart[2] = tI + tU;
    OB.chunk = (tI + tU + NCTA_GEMM - 1) / NCTA_GEMM;
    mma_gemm_out<<<NCTA_GEMM, 256, GEMM_SMEM>>>(OB);

    (void)n_in; (void)out_size;
}

// round 17
// speedup vs baseline: 1.1227x; 1.1227x over previous
#include <cuda_runtime.h>
#include <cuda_bf16.h>
#include <math.h>
#include <stdint.h>

// ---------------------------------------------------------------------------
// MultiModalFusionGAT — mma.sync bf16x3 GEMM + CSR-gather edge phase.
//  * R14 GEMM layout restored (two independent LDS.64 B-fragment loads —
//    the LDS.128 interleave regressed: fewer instrs but worse scheduling)
//  * int4-vectorized scan kept (independent win)
//  * persistent projection + output GEMMs, hist fused, zero fused into prep
// ---------------------------------------------------------------------------

#define HID 128

// scratch layout (floats)
#define OFF_Q_USER   0ll
#define OFF_Q_ITEM   2560000ll
#define OFF_KV_USER  8960000ll    // 20000 * 256 (kr | vr interleaved)
#define OFF_KV_ITEM  14080000ll   // 50000 * 256
#define OFF_KV_TASTE 26880000ll   // 50000 * 256
#define OFF_KV_IMAGE 39680000ll   // 50000 * 256
#define OFF_CSRBASE  52480000ll   // int region
#define OFF_GEL_ITEM 62000000ll
#define OFF_GEL_USER 68400000ll
#define OFF_WFRAG    70960000ll   // 12 mats x 16384 u32 (hi 8192 + lo 8192)
#define OFF_BIAS     71156608ll   // 12 x 128 floats
#define SCRATCH_TOTAL 71158144ll

// int offsets inside the CSR region (units: int32)
#define ICSR_I   0          // 600000 entries (item edges, packed src|seg<<16)
#define ICSR_U   600000     // 500000 entries (user edges, src)
#define ISTART_I 1100000    // 50001
#define ISTART_U 1150004    // 20001
#define ICNT_I   1170008    // 50000
#define ICNT_U   1220008    // 20000  (cnt arrays contiguous: 70000 total)

#define NCTA_GEMM 296       // persistent GEMM CTAs (2 per SM, one wave)
#define GEMM_SMEM 65536

__device__ float g_scratch[SCRATCH_TOTAL];

struct EdgeIO {
    const int* src[4];
    const int* dst[4];
    int off[5];
};

struct GemmBatch {
    const float* X[10];
    const uint32_t* W[10];
    const float* B[10];
    float* Y[10];
    int N[10];
    int YS[10];        // output row stride (floats)
    int tileStart[11]; // prefix sums of per-matrix tile counts
    int chunk;         // tiles per persistent CTA
    EdgeIO E;          // for the fused hist slice (blockIdx.y == 1)
    int* cntI;
    int* cntU;
};

struct OutBatch {
    const float* X[2];
    const uint32_t* W[2];
    const float* B[2];
    float* Y[2];
    const float* Res[2];
    const float* Skip;
    int N[2];
    int tileStart[3];
    int chunk;
};

struct GatherIO {
    const float* Qi; const float* Qu;
    const float* KV[4];           // interleaved kr|vr, 256 floats/node
    const int* csrI; const int* csrU;
    const int* startI; const int* startU;
    float* gelI; float* gelU;
    const float* prel;
    int nI, nU;
};

// ---------------------------------------------------------------------------
__device__ __forceinline__ float foldW(int m, int k, int n,
        const float* __restrict__ Wk, const float* __restrict__ Wv,
        const float* __restrict__ Wq, const float* __restrict__ Wo,
        const float* __restrict__ a_rel, const float* __restrict__ m_rel) {
    if (m < 8) {
        int r = m & 3;
        int h = n >> 4, e = n & 15;
        int tsrc = (r == 0) ? 2 : (r == 1) ? 3 : (r == 2) ? 0 : 1;
        const float* Wsrc = (m < 4) ? Wk : Wv;
        const float* rel  = (m < 4) ? a_rel : m_rel;
        const float* wrow = Wsrc + tsrc * 16384 + k * 128 + h * 16;
        const float* arow = rel + r * 2048 + h * 256;
        float s = 0.f;
        #pragma unroll
        for (int d = 0; d < 16; d++) s += wrow[d] * arow[d * 16 + e];
        return s;
    } else if (m < 10) {
        return Wq[(m - 8) * 16384 + k * 128 + n];
    }
    return Wo[(m - 10) * 16384 + k * 128 + n];
}

__device__ __forceinline__ uint32_t packbf2(float a, float b) {
    __nv_bfloat16 ha = __float2bfloat16(a), hb = __float2bfloat16(b);
    return (uint32_t)__bfloat16_as_ushort(ha)
         | ((uint32_t)__bfloat16_as_ushort(hb) << 16);
}

// prep: weights -> fragment layout (hi 8192 u32 | lo 8192 u32), bias fold,
// CSR counter zeroing (fused)
#define PREP_W   98304
#define PREP_B   (PREP_W + 1536)
#define PREP_Z   (PREP_B + 70000)
__global__ void prep_kernel(const float* __restrict__ Wk, const float* __restrict__ bk,
                            const float* __restrict__ Wq, const float* __restrict__ bq,
                            const float* __restrict__ Wv, const float* __restrict__ bv,
                            const float* __restrict__ a_rel, const float* __restrict__ m_rel,
                            const float* __restrict__ Wo, const float* __restrict__ bo,
                            uint32_t* __restrict__ Wfrag, float* __restrict__ Bias,
                            int* __restrict__ cnt) {
    int idx = blockIdx.x * blockDim.x + threadIdx.x;
    if (idx < PREP_W) {
        int m = idx >> 13;
        int rest = idx & 8191;
        int kc = rest >> 10;
        int rest2 = rest & 1023;
        int nt = rest2 >> 6;
        int e  = rest2 & 63;
        int lane = e >> 1, r = e & 1;
        int n  = nt * 8 + (lane >> 2);
        int k0 = kc * 16 + (lane & 3) * 2 + r * 8;
        float v0 = foldW(m, k0,     n, Wk, Wv, Wq, Wo, a_rel, m_rel);
        float v1 = foldW(m, k0 + 1, n, Wk, Wv, Wq, Wo, a_rel, m_rel);
        __nv_bfloat16 h0 = __float2bfloat16(v0), h1 = __float2bfloat16(v1);
        float l0 = v0 - __bfloat162float(h0), l1 = v1 - __bfloat162float(h1);
        uint32_t hi = (uint32_t)__bfloat16_as_ushort(h0)
                    | ((uint32_t)__bfloat16_as_ushort(h1) << 16);
        uint32_t lo = packbf2(l0, l1);
        size_t base = (size_t)m * 16384 + ((kc * 16 + nt) * 64 + e);
        Wfrag[base] = hi;
        Wfrag[base + 8192] = lo;
    } else if (idx < PREP_B) {
        int j = idx - PREP_W;
        int m = j >> 7, n = j & 127;
        float bval;
        if (m < 8) {
            int r = m & 3;
            int h = n >> 4, e2 = n & 15;
            int tsrc = (r == 0) ? 2 : (r == 1) ? 3 : (r == 2) ? 0 : 1;
            const float* bsrc = (m < 4) ? bk : bv;
            const float* rel  = (m < 4) ? a_rel : m_rel;
            const float* brow = bsrc + tsrc * 128 + h * 16;
            const float* arow = rel + r * 2048 + h * 256;
            float sb = 0.f;
            #pragma unroll
            for (int d = 0; d < 16; d++) sb += brow[d] * arow[d * 16 + e2];
            bval = sb;
        } else if (m < 10) {
            bval = bq[(m - 8) * 128 + n];
        } else {
            bval = bo[(m - 10) * 128 + n];
        }
        Bias[m * 128 + n] = bval;
    } else if (idx < PREP_Z) {
        cnt[idx - PREP_B] = 0;   // cntI | cntU contiguous (70000 ints)
    }
}

// ---------------------------------------------------------------------------
__device__ __forceinline__ void mma16816(float c[4], const uint32_t a[4],
                                         uint32_t b0, uint32_t b1) {
    asm volatile(
        "mma.sync.aligned.m16n8k16.row.col.f32.bf16.bf16.f32 "
        "{%0,%1,%2,%3}, {%4,%5,%6,%7}, {%8,%9}, {%0,%1,%2,%3};"
        : "+f"(c[0]), "+f"(c[1]), "+f"(c[2]), "+f"(c[3])
        : "r"(a[0]), "r"(a[1]), "r"(a[2]), "r"(a[3]), "r"(b0), "r"(b1));
}

__device__ __forceinline__ void split4(const float2& a, const float2& b,
                                       uint32_t& h01, uint32_t& l01,
                                       uint32_t& h23, uint32_t& l23) {
    __nv_bfloat16 ha = __float2bfloat16(a.x), hb = __float2bfloat16(a.y);
    __nv_bfloat16 hc = __float2bfloat16(b.x), hd = __float2bfloat16(b.y);
    h01 = (uint32_t)__bfloat16_as_ushort(ha) | ((uint32_t)__bfloat16_as_ushort(hb) << 16);
    h23 = (uint32_t)__bfloat16_as_ushort(hc) | ((uint32_t)__bfloat16_as_ushort(hd) << 16);
    l01 = packbf2(a.x - __bfloat162float(ha), a.y - __bfloat162float(hb));
    l23 = packbf2(b.x - __bfloat162float(hc), b.y - __bfloat162float(hd));
}

// Core 128x128 tile GEMM (bf16x3), pipelined kc loop; two LDS.64 B loads.
__device__ __forceinline__ void gemm_tile(
        const float* __restrict__ X, const uint32_t* __restrict__ sW,
        const float* __restrict__ Bias, float* __restrict__ Y, int N, int tile0,
        int ystride, int mode, const float* __restrict__ Res, float g, float omg) {
    int tid = threadIdx.x;
    int warp = tid >> 5, lane = tid & 31;
    int rlo = tile0 + warp * 16 + (lane >> 2);
    int rhi = rlo + 8;
    bool oklo = rlo < N, okhi = rhi < N;
    const float* xlo = X + (size_t)rlo * 128;
    const float* xhi = X + (size_t)rhi * 128;
    int kb = (lane & 3) * 2;

    float C[16][4];
    #pragma unroll
    for (int nt = 0; nt < 16; nt++)
        #pragma unroll
        for (int j = 0; j < 4; j++) C[nt][j] = 0.f;

    float2 z2 = make_float2(0.f, 0.f);
    float2 p00 = oklo ? *(const float2*)(xlo + kb)     : z2;
    float2 p01 = oklo ? *(const float2*)(xlo + kb + 8) : z2;
    float2 p10 = okhi ? *(const float2*)(xhi + kb)     : z2;
    float2 p11 = okhi ? *(const float2*)(xhi + kb + 8) : z2;

    #pragma unroll 1
    for (int kc = 0; kc < 8; kc++) {
        float2 c00 = p00, c01 = p01, c10 = p10, c11 = p11;
        if (kc < 7) {
            int o = (kc + 1) * 16 + kb;
            p00 = oklo ? *(const float2*)(xlo + o)     : z2;
            p01 = oklo ? *(const float2*)(xlo + o + 8) : z2;
            p10 = okhi ? *(const float2*)(xhi + o)     : z2;
            p11 = okhi ? *(const float2*)(xhi + o + 8) : z2;
        }
        uint32_t ahi[4], alo[4];
        split4(c00, c10, ahi[0], alo[0], ahi[1], alo[1]);
        split4(c01, c11, ahi[2], alo[2], ahi[3], alo[3]);
        #pragma unroll
        for (int nt = 0; nt < 16; nt++) {
            uint32_t off = (uint32_t)((kc * 16 + nt) * 64 + lane * 2);
            uint2 bh = *(const uint2*)&sW[off];
            uint2 bl = *(const uint2*)&sW[off + 8192];
            mma16816(C[nt], ahi, bh.x, bh.y);
            mma16816(C[nt], alo, bh.x, bh.y);
            mma16816(C[nt], ahi, bl.x, bl.y);
        }
    }

    #pragma unroll
    for (int nt = 0; nt < 16; nt++) {
        int col = nt * 8 + kb;
        float2 b = *(const float2*)(Bias + col);
        if (oklo) {
            float2 o = make_float2(C[nt][0] + b.x, C[nt][1] + b.y);
            if (mode == 1) {
                float2 rv = *(const float2*)(Res + (size_t)rlo * 128 + col);
                o.x = g * o.x + omg * rv.x;
                o.y = g * o.y + omg * rv.y;
            }
            *(float2*)(Y + (size_t)rlo * ystride + col) = o;
        }
        if (okhi) {
            float2 o = make_float2(C[nt][2] + b.x, C[nt][3] + b.y);
            if (mode == 1) {
                float2 rv = *(const float2*)(Res + (size_t)rhi * 128 + col);
                o.x = g * o.x + omg * rv.x;
                o.y = g * o.y + omg * rv.y;
            }
            *(float2*)(Y + (size_t)rhi * ystride + col) = o;
        }
    }
}

// persistent batched projections (grid.y==0) + fused hist (grid.y==1)
__global__ void __launch_bounds__(256) mma_gemm_batch(GemmBatch P) {
    if (blockIdx.y == 1) {
        int total = P.E.off[4];
        int stride = gridDim.x * 256;
        for (int g = blockIdx.x * 256 + threadIdx.x; g < total; g += stride) {
            int seg = (g >= P.E.off[1]) + (g >= P.E.off[2]) + (g >= P.E.off[3]);
            int e = g - P.E.off[seg];
            int d = P.E.dst[seg][e];
            atomicAdd((seg < 3) ? (P.cntI + d) : (P.cntU + d), 1);
        }
        return;
    }
    extern __shared__ uint32_t sW[];
    int total = P.tileStart[10];
    int t0 = blockIdx.x * P.chunk;
    int t1 = t0 + P.chunk;
    if (t1 > total) t1 = total;
    int cur = -1;
    for (int t = t0; t < t1; t++) {
        if (cur < 0 || t >= P.tileStart[cur + 1]) {
            int m = (cur < 0) ? 0 : cur + 1;
            while (t >= P.tileStart[m + 1]) m++;
            __syncthreads();   // all warps done reading old weights
            const uint4* src = (const uint4*)P.W[m];
            uint4* dst = (uint4*)sW;
            int tid = threadIdx.x;
            #pragma unroll
            for (int i = 0; i < 16; i++) dst[tid + i * 256] = src[tid + i * 256];
            __syncthreads();
            cur = m;
        }
        gemm_tile(P.X[cur], sW, P.B[cur], P.Y[cur], P.N[cur],
                  (t - P.tileStart[cur]) * 128, P.YS[cur], 0, nullptr, 1.f, 0.f);
    }
}

// persistent fused output GEMMs with sigmoid-gated residual
__global__ void __launch_bounds__(256) mma_gemm_out(OutBatch P) {
    extern __shared__ uint32_t sW[];
    int total = P.tileStart[2];
    int t0 = blockIdx.x * P.chunk;
    int t1 = t0 + P.chunk;
    if (t1 > total) t1 = total;
    int cur = -1;
    float g = 1.f, omg = 0.f;
    for (int t = t0; t < t1; t++) {
        if (cur < 0 || t >= P.tileStart[cur + 1]) {
            int m = (cur < 0) ? 0 : cur + 1;
            while (t >= P.tileStart[m + 1]) m++;
            __syncthreads();
            const uint4* src = (const uint4*)P.W[m];
            uint4* dst = (uint4*)sW;
            int tid = threadIdx.x;
            #pragma unroll
            for (int i = 0; i < 16; i++) dst[tid + i * 256] = src[tid + i * 256];
            __syncthreads();
            cur = m;
            g = 1.f / (1.f + expf(-P.Skip[m]));
            omg = 1.f - g;
        }
        gemm_tile(P.X[cur], sW, P.B[cur], P.Y[cur], P.N[cur],
                  (t - P.tileStart[cur]) * 128, 128, 1, P.Res[cur], g, omg);
    }
}

// ---------------------------------------------------------------------------
// vectorized block scan (int4, 4096 elements per iteration); resets cnt to 0
__global__ void scan_kernel(int* __restrict__ cntI, int* __restrict__ startI, int nI,
                            int* __restrict__ cntU, int* __restrict__ startU, int nU) {
    int* cnt   = blockIdx.x ? cntU : cntI;
    int* start = blockIdx.x ? startU : startI;
    int n      = blockIdx.x ? nU : nI;     // multiple of 4
    __shared__ int wsum[32];
    __shared__ int s_carry;
    int tid = threadIdx.x, lane = tid & 31, wid = tid >> 5;
    if (tid == 0) s_carry = 0;
    __syncthreads();
    for (int base = 0; base < n; base += 4096) {
        int i4 = base + tid * 4;
        int4 v = make_int4(0, 0, 0, 0);
        if (i4 < n) {
            v = *(const int4*)(cnt + i4);
            *(int4*)(cnt + i4) = make_int4(0, 0, 0, 0);
        }
        int s = v.x + v.y + v.z + v.w;
        int incl = s;
        #pragma unroll
        for (int o = 1; o < 32; o <<= 1) {
            int t = __shfl_up_sync(0xFFFFFFFFu, incl, o);
            if (lane >= o) incl += t;
        }
        if (lane == 31) wsum[wid] = incl;
        __syncthreads();
        if (wid == 0) {
            int w = wsum[lane];
            int wi = w;
            #pragma unroll
            for (int o = 1; o < 32; o <<= 1) {
                int t = __shfl_up_sync(0xFFFFFFFFu, wi, o);
                if (lane >= o) wi += t;
            }
            wsum[lane] = wi - w;
        }
        __syncthreads();
        int excl = incl - s + wsum[wid] + s_carry;
        if (i4 < n) {
            int4 o;
            o.x = excl;
            o.y = excl + v.x;
            o.z = o.y + v.y;
            o.w = o.z + v.z;
            *(int4*)(start + i4) = o;
        }
        __syncthreads();
        if (tid == 1023) s_carry = excl + s;
        __syncthreads();
    }
    if (tid == 0) start[n] = s_carry;
}

__global__ void scatter_kernel(EdgeIO E,
                               const int* __restrict__ startI, const int* __restrict__ startU,
                               int* __restrict__ cntI, int* __restrict__ cntU,
                               int* __restrict__ csrI, int* __restrict__ csrU) {
    int g = blockIdx.x * 256 + threadIdx.x;
    if (g >= E.off[4]) return;
    int seg = (g >= E.off[1]) + (g >= E.off[2]) + (g >= E.off[3]);
    int e = g - E.off[seg];
    int d = E.dst[seg][e];
    int s = E.src[seg][e];
    if (seg < 3) {
        int pos = startI[d] + atomicAdd(cntI + d, 1);
        csrI[pos] = s | (seg << 16);
    } else {
        int pos = startU[d] + atomicAdd(cntU + d, 1);
        csrU[pos] = s;
    }
}

// warp-per-dst gather, unrolled x2: softmax aggregate + inline GELU
__global__ void __launch_bounds__(256) gather_kernel(GatherIO P) {
    int w = blockIdx.x * 8 + (threadIdx.x >> 5);
    int lane = threadIdx.x & 31;
    int h = lane >> 2;
    bool item = w < P.nI;
    int d = item ? w : w - P.nI;
    if (!item && d >= P.nU) return;

    const float* q = (item ? P.Qi : P.Qu) + (size_t)d * 128;
    float4 qv = *(const float4*)(q + lane * 4);
    const int* csr = item ? P.csrI : P.csrU;
    int js = item ? P.startI[d] : P.startU[d];
    int je = item ? P.startI[d + 1] : P.startU[d + 1];
    float p0, p1, p2;
    if (item) { p0 = P.prel[h]; p1 = P.prel[8 + h]; p2 = P.prel[16 + h]; }
    else      { p0 = p1 = p2 = P.prel[24 + h]; }

    float4 acc = make_float4(0.f, 0.f, 0.f, 0.f);
    float den = 0.f;
    int j = js;
    for (; j + 1 < je; j += 2) {
        int e0 = csr[j], e1 = csr[j + 1];
        int s0 = e0 & 0xFFFF, s1 = e1 & 0xFFFF;
        int g0 = item ? (e0 >> 16) : 3, g1 = item ? (e1 >> 16) : 3;
        const float* kv0b = P.KV[g0] + (size_t)s0 * 256;
        const float* kv1b = P.KV[g1] + (size_t)s1 * 256;
        float4 k0 = *(const float4*)(kv0b + lane * 4);
        float4 v0 = *(const float4*)(kv0b + 128 + lane * 4);
        float4 k1 = *(const float4*)(kv1b + lane * 4);
        float4 v1 = *(const float4*)(kv1b + 128 + lane * 4);
        float pa = qv.x * k0.x + qv.y * k0.y + qv.z * k0.z + qv.w * k0.w;
        float pb = qv.x * k1.x + qv.y * k1.y + qv.z * k1.z + qv.w * k1.w;
        pa += __shfl_xor_sync(0xFFFFFFFFu, pa, 1);
        pb += __shfl_xor_sync(0xFFFFFFFFu, pb, 1);
        pa += __shfl_xor_sync(0xFFFFFFFFu, pa, 2);
        pb += __shfl_xor_sync(0xFFFFFFFFu, pb, 2);
        float pr0 = item ? ((g0 == 0) ? p0 : ((g0 == 1) ? p1 : p2)) : p0;
        float pr1 = item ? ((g1 == 0) ? p0 : ((g1 == 1) ? p1 : p2)) : p0;
        float ex0 = __expf(pa * pr0 * 0.25f);
        float ex1 = __expf(pb * pr1 * 0.25f);
        den += ex0 + ex1;
        acc.x += ex0 * v0.x + ex1 * v1.x;
        acc.y += ex0 * v0.y + ex1 * v1.y;
        acc.z += ex0 * v0.z + ex1 * v1.z;
        acc.w += ex0 * v0.w + ex1 * v1.w;
    }
    if (j < je) {
        int e0 = csr[j];
        int s0 = e0 & 0xFFFF;
        int g0 = item ? (e0 >> 16) : 3;
        const float* kv0b = P.KV[g0] + (size_t)s0 * 256;
        float4 k0 = *(const float4*)(kv0b + lane * 4);
        float4 v0 = *(const float4*)(kv0b + 128 + lane * 4);
        float pa = qv.x * k0.x + qv.y * k0.y + qv.z * k0.z + qv.w * k0.w;
        pa += __shfl_xor_sync(0xFFFFFFFFu, pa, 1);
        pa += __shfl_xor_sync(0xFFFFFFFFu, pa, 2);
        float pr0 = item ? ((g0 == 0) ? p0 : ((g0 == 1) ? p1 : p2)) : p0;
        float ex0 = __expf(pa * pr0 * 0.25f);
        den += ex0;
        acc.x += ex0 * v0.x; acc.y += ex0 * v0.y;
        acc.z += ex0 * v0.z; acc.w += ex0 * v0.w;
    }
    float inv = 1.f / (den + 1e-16f);
    const float RS2 = 0.70710678118654752f;
    float4 o;
    float v;
    v = acc.x * inv; o.x = 0.5f * v * (1.f + erff(v * RS2));
    v = acc.y * inv; o.y = 0.5f * v * (1.f + erff(v * RS2));
    v = acc.z * inv; o.z = 0.5f * v * (1.f + erff(v * RS2));
    v = acc.w * inv; o.w = 0.5f * v * (1.f + erff(v * RS2));
    float* out = (item ? P.gelI : P.gelU) + (size_t)d * 128 + lane * 4;
    *(float4*)out = o;
}

// ---------------------------------------------------------------------------
extern "C" void kernel_launch(void* const* d_in, const int* in_sizes, int n_in,
                              void* d_out, int out_size) {
    const float* x_user = (const float*)d_in[0];
    const float* x_item = (const float*)d_in[1];
    const float* x_taste = (const float*)d_in[2];
    const float* x_image = (const float*)d_in[3];
    const float* Wk = (const float*)d_in[4];
    const float* bk = (const float*)d_in[5];
    const float* Wq = (const float*)d_in[6];
    const float* bq = (const float*)d_in[7];
    const float* Wv = (const float*)d_in[8];
    const float* bv = (const float*)d_in[9];
    const float* a_rel = (const float*)d_in[10];
    const float* m_rel = (const float*)d_in[11];
    const float* p_rel = (const float*)d_in[12];
    const float* Wo = (const float*)d_in[13];
    const float* bo = (const float*)d_in[14];
    const float* skip = (const float*)d_in[15];
    const int* ti_src = (const int*)d_in[16];
    const int* ti_dst = (const int*)d_in[17];
    const int* im_src = (const int*)d_in[18];
    const int* im_dst = (const int*)d_in[19];
    const int* ub_src = (const int*)d_in[20];
    const int* ub_dst = (const int*)d_in[21];
    const int* bu_src = (const int*)d_in[22];
    const int* bu_dst = (const int*)d_in[23];

    int nUser = in_sizes[0] / HID;
    int nItem = in_sizes[1] / HID;
    int nTaste = in_sizes[2] / HID;
    int nImage = in_sizes[3] / HID;
    int eTI = in_sizes[16], eIM = in_sizes[18], eUB = in_sizes[20], eBU = in_sizes[22];

    float* S = nullptr;
    cudaGetSymbolAddress((void**)&S, g_scratch);
    uint32_t* Wfrag = (uint32_t*)(S + OFF_WFRAG);
    float* Bias = S + OFF_BIAS;
    int* I = (int*)(S + OFF_CSRBASE);

    cudaFuncSetAttribute(mma_gemm_batch,
                         cudaFuncAttributeMaxDynamicSharedMemorySize, GEMM_SMEM);
    cudaFuncSetAttribute(mma_gemm_out,
                         cudaFuncAttributeMaxDynamicSharedMemorySize, GEMM_SMEM);

    // edge tables
    EdgeIO E;
    E.src[0] = ti_src; E.dst[0] = ti_dst;
    E.src[1] = im_src; E.dst[1] = im_dst;
    E.src[2] = ub_src; E.dst[2] = ub_dst;
    E.src[3] = bu_src; E.dst[3] = bu_dst;
    E.off[0] = 0;
    E.off[1] = eTI;
    E.off[2] = eTI + eIM;
    E.off[3] = eTI + eIM + eUB;
    E.off[4] = eTI + eIM + eUB + eBU;
    int eTotal = E.off[4];

    // 1) prep weights + bias + zero CSR counters (one launch)
    prep_kernel<<<(PREP_Z + 255) / 256, 256>>>(
        Wk, bk, Wq, bq, Wv, bv, a_rel, m_rel, Wo, bo, Wfrag, Bias, I + ICNT_I);

    // 2) persistent projection GEMMs + hist, one launch
    GemmBatch GB;
    const float* xs[10] = {x_user, x_item, x_user, x_user, x_item,
                           x_item, x_taste, x_taste, x_image, x_image};
    int mats[10]        = {8, 9, 2, 6, 3, 7, 0, 4, 1, 5};
    long long offs[10]  = {OFF_Q_USER, OFF_Q_ITEM,
                           OFF_KV_USER, OFF_KV_USER + 128,
                           OFF_KV_ITEM, OFF_KV_ITEM + 128,
                           OFF_KV_TASTE, OFF_KV_TASTE + 128,
                           OFF_KV_IMAGE, OFF_KV_IMAGE + 128};
    int strides[10] = {128, 128, 256, 256, 256, 256, 256, 256, 256, 256};
    int ns[10] = {nUser, nItem, nUser, nUser, nItem, nItem, nTaste, nTaste, nImage, nImage};
    int tsum = 0;
    for (int i = 0; i < 10; i++) {
        GB.X[i] = xs[i];
        GB.W[i] = Wfrag + (size_t)mats[i] * 16384;
        GB.B[i] = Bias + mats[i] * 128;
        GB.Y[i] = S + offs[i];
        GB.N[i] = ns[i];
        GB.YS[i] = strides[i];
        GB.tileStart[i] = tsum;
        tsum += (ns[i] + 127) / 128;
    }
    GB.tileStart[10] = tsum;
    GB.chunk = (tsum + NCTA_GEMM - 1) / NCTA_GEMM;
    GB.E = E;
    GB.cntI = I + ICNT_I;
    GB.cntU = I + ICNT_U;
    mma_gemm_batch<<<dim3(NCTA_GEMM, 2), 256, GEMM_SMEM>>>(GB);

    // 3) CSR: scan + scatter
    scan_kernel<<<2, 1024>>>(I + ICNT_I, I + ISTART_I, nItem,
                             I + ICNT_U, I + ISTART_U, nUser);
    scatter_kernel<<<(eTotal + 255) / 256, 256>>>(E, I + ISTART_I, I + ISTART_U,
                                                  I + ICNT_I, I + ICNT_U,
                                                  I + ICSR_I, I + ICSR_U);

    // 4) gather: softmax aggregate + GELU
    GatherIO G;
    G.Qi = S + OFF_Q_ITEM;
    G.Qu = S + OFF_Q_USER;
    G.KV[0] = S + OFF_KV_TASTE;
    G.KV[1] = S + OFF_KV_IMAGE;
    G.KV[2] = S + OFF_KV_USER;
    G.KV[3] = S + OFF_KV_ITEM;
    G.csrI = I + ICSR_I;   G.csrU = I + ICSR_U;
    G.startI = I + ISTART_I; G.startU = I + ISTART_U;
    G.gelI = S + OFF_GEL_ITEM; G.gelU = S + OFF_GEL_USER;
    G.prel = p_rel;
    G.nI = nItem; G.nU = nUser;
    int warps = nItem + nUser;
    gather_kernel<<<(warps + 7) / 8, 256>>>(G);

    // 5) persistent fused output projections with sigmoid-gated residual
    float* out_i = (float*)d_out;
    float* out_u = (float*)d_out + (size_t)nItem * HID;
    OutBatch OB;
    OB.X[0] = S + OFF_GEL_ITEM; OB.X[1] = S + OFF_GEL_USER;
    OB.W[0] = Wfrag + 10ull * 16384; OB.W[1] = Wfrag + 11ull * 16384;
    OB.B[0] = Bias + 10 * 128; OB.B[1] = Bias + 11 * 128;
    OB.Y[0] = out_i; OB.Y[1] = out_u;
    OB.Res[0] = x_item; OB.Res[1] = x_user;
    OB.Skip = skip;
    OB.N[0] = nItem; OB.N[1] = nUser;
    int tI = (nItem + 127) / 128, tU = (nUser + 127) / 128;
    OB.tileStart[0] = 0;
    OB.tileStart[1] = tI;
    OB.tileStart[2] = tI + tU;
    OB.chunk = (tI + tU + NCTA_GEMM - 1) / NCTA_GEMM;
    mma_gemm_out<<<NCTA_GEMM, 256, GEMM_SMEM>>>(OB);

    (void)n_in; (void)out_size;
}